// round 5
// baseline (speedup 1.0000x reference)
#include <cuda_runtime.h>
#include <cstdint>

#define BATCH 4
#define SEQ   1024
#define EMB   768
#define HEADS 12
#define HDIM  64
#define BH    (BATCH*HEADS)    // 48

#define RS_ELEMS (BH * HEADS * EMB)      // RS[b*12+h][c][j]
#define G_ELEMS  (BATCH * EMB)

// Single scratch blob so one memsetAsync zeroes both accumulators.
// Layout: [0, RS_ELEMS) = RS, [RS_ELEMS, RS_ELEMS+G_ELEMS) = G
__device__ float g_Acc[RS_ELEMS + G_ELEMS];

// ---------------------------------------------------------------------------
// K1: segmented scan over value.
// grid = (b,c,tile): ((b*12+c)<<3)|t, 384 blocks x 768 threads (j).
// Rows s in [t*128, t*128+128); h(s) = (768s+64c)>>16 partitions rows into
// <=3 uniform segments per tile; flush each segment's column sum via atomicAdd
// into RS[(b*12+h)*12+c][j].
// ---------------------------------------------------------------------------
__global__ void __launch_bounds__(768) scan_kernel(const float* __restrict__ value)
{
    const int x = blockIdx.x;
    const int t  = x & 7;
    const int bc = x >> 3;           // b*12 + c
    const int b = bc / HEADS;
    const int c = bc % HEADS;
    const int j = threadIdx.x;

    const int s0 = t * 128;
    const float* vp = value + ((size_t)b * SEQ + s0) * EMB + j;

    int h_cur = (768 * s0 + 64 * c) >> 16;
    // next s where h increments: smallest s with 768s+64c >= 65536*(h+1)
    int s_next = (65536 * (h_cur + 1) - 64 * c + EMB - 1) / EMB;

    float acc = 0.0f;
    #pragma unroll 8
    for (int s = s0; s < s0 + 128; s++) {
        if (s == s_next) {
            atomicAdd(&g_Acc[((size_t)(b * HEADS + h_cur) * HEADS + c) * EMB + j], acc);
            acc = 0.0f;
            h_cur++;
            s_next = (65536 * (h_cur + 1) - 64 * c + EMB - 1) / EMB;
        }
        acc += vp[(size_t)(s - s0) * EMB];
    }
    atomicAdd(&g_Acc[((size_t)(b * HEADS + h_cur) * HEADS + c) * EMB + j], acc);
}

// ---------------------------------------------------------------------------
// K2: K-split GEMM.  grid = 144 blocks (c = blk/12, jt = blk%12), 256 threads.
// Ws = Wv[64c..64c+63][jt*64..+63], As = RS[0..47][c][jt*64..+63]
// partial[bh][d] = sum_k As[bh][k]*Ws[d][k]  -> atomicAdd into G.
// ---------------------------------------------------------------------------
__global__ void __launch_bounds__(256) kgemm_kernel(const float* __restrict__ Wv)
{
    const int c  = blockIdx.x / 12;
    const int jt = blockIdx.x % 12;
    const int t = threadIdx.x;

    __shared__ float Ws[64][65];
    __shared__ float As[48][65];

    #pragma unroll
    for (int i = 0; i < 4; i++) {
        int f = t + 256 * i;
        int r = f >> 4, c4 = f & 15;
        float4 v = *(const float4*)(Wv + (size_t)(64 * c + r) * EMB + jt * 64 + c4 * 4);
        Ws[r][c4 * 4 + 0] = v.x; Ws[r][c4 * 4 + 1] = v.y;
        Ws[r][c4 * 4 + 2] = v.z; Ws[r][c4 * 4 + 3] = v.w;
    }
    #pragma unroll
    for (int i = 0; i < 3; i++) {
        int f = t + 256 * i;
        int r = f >> 4, c4 = f & 15;     // r = bh 0..47
        float4 v = *(const float4*)(g_Acc + ((size_t)r * HEADS + c) * EMB + jt * 64 + c4 * 4);
        As[r][c4 * 4 + 0] = v.x; As[r][c4 * 4 + 1] = v.y;
        As[r][c4 * 4 + 2] = v.z; As[r][c4 * 4 + 3] = v.w;
    }
    __syncthreads();

    const int tx = t & 15;     // 4 d's
    const int ty = t >> 4;     // 3 bh's

    float acc[3][4] = {};
    #pragma unroll 8
    for (int k = 0; k < 64; k++) {
        float a[3], bb[4];
        #pragma unroll
        for (int u = 0; u < 3; u++) a[u] = As[ty * 3 + u][k];
        #pragma unroll
        for (int v = 0; v < 4; v++) bb[v] = Ws[tx * 4 + v][k];
        #pragma unroll
        for (int u = 0; u < 3; u++)
            #pragma unroll
            for (int v = 0; v < 4; v++)
                acc[u][v] = fmaf(a[u], bb[v], acc[u][v]);
    }

    #pragma unroll
    for (int u = 0; u < 3; u++) {
        int bh = ty * 3 + u;
        int b = bh / HEADS, h = bh % HEADS;
        float* gp = g_Acc + RS_ELEMS + b * EMB + h * HDIM + tx * 4;
        #pragma unroll
        for (int v = 0; v < 4; v++)
            atomicAdd(gp + v, acc[u][v]);
    }
}

// ---------------------------------------------------------------------------
// K3: out[b, q, :] = G[b, :]   512 blocks x 768 thr, 8 rows per block.
// ---------------------------------------------------------------------------
__global__ void __launch_bounds__(768) broadcast_kernel(float* __restrict__ out)
{
    const int t = threadIdx.x;
    const int row0 = blockIdx.x * 8;
    const int c4 = t % 192;
    const int r  = t / 192;

    const float* G = g_Acc + RS_ELEMS;
    const int row = row0 + r;
    const int b0 = (row)     >> 10;
    const int b1 = (row + 4) >> 10;

    float4 v0 = ((const float4*)(G + b0 * EMB))[c4];
    ((float4*)(out + (size_t)row * EMB))[c4] = v0;

    float4 v1 = (b1 == b0) ? v0 : ((const float4*)(G + b1 * EMB))[c4];
    ((float4*)(out + (size_t)(row + 4) * EMB))[c4] = v1;
}

// ---------------------------------------------------------------------------
extern "C" void kernel_launch(void* const* d_in, const int* in_sizes, int n_in,
                              void* d_out, int out_size)
{
    // metadata order: key, query, value, Wk, Wq, Wv
    const float* value = (const float*)d_in[2];
    const float* Wv    = (const float*)d_in[5];
    float* out = (float*)d_out;

    float* acc;
    cudaGetSymbolAddress((void**)&acc, g_Acc);

    cudaMemsetAsync(acc, 0, (RS_ELEMS + G_ELEMS) * sizeof(float));
    scan_kernel<<<BH * HEADS / 12 * 8 * 12 / 12, 768>>>(value); // 384 blocks
    kgemm_kernel<<<144, 256>>>(Wv);
    broadcast_kernel<<<512, 768>>>(out);
}

// round 6
// speedup vs baseline: 1.2289x; 1.2289x over previous
#include <cuda_runtime.h>
#include <cstdint>

#define BATCH 4
#define SEQ   1024
#define EMB   768
#define HEADS 12
#define HDIM  64
#define BH    (BATCH*HEADS)    // 48

#define RS_ELEMS (BH * HEADS * EMB)      // RS[(b*12+h)*12+c][j]
#define G_ELEMS  (BATCH * EMB)

// Single scratch blob so one memsetAsync zeroes both accumulators.
__device__ float g_Acc[RS_ELEMS + G_ELEMS];

// ---------------------------------------------------------------------------
// K1: single-pass segmented scan. Each value element read ONCE; each thread
// carries 12 register accumulators (one per column-group c) and flushes at
// the (warp-uniform, <=1 per tile per c) head boundary via atomicAdd.
// grid = 256: x = ((b*32 + tile) << 1) | jhalf ; block = 384 threads.
// ---------------------------------------------------------------------------
__global__ void __launch_bounds__(384) scan_kernel(const float* __restrict__ value)
{
    const int x  = blockIdx.x;
    const int jh = x & 1;
    const int bt = x >> 1;
    const int b  = bt >> 5;          // 0..3
    const int t  = bt & 31;          // 32 tiles of 32 rows
    const int j  = jh * 384 + threadIdx.x;

    const int s0 = t * 32;
    const float* vp = value + ((size_t)b * SEQ + s0) * EMB + j;

    float acc[12];
    int   hc[12];
    int   sb[12];
    #pragma unroll
    for (int c = 0; c < 12; c++) {
        acc[c] = 0.0f;
        hc[c]  = (768 * s0 + 64 * c) >> 16;
        sb[c]  = (65536 * (hc[c] + 1) - 64 * c + 767) / 768;  // next boundary s
    }

    #pragma unroll 4
    for (int i = 0; i < 32; i++) {
        const int s = s0 + i;
        const float v = vp[(size_t)i * EMB];
        #pragma unroll
        for (int c = 0; c < 12; c++) {
            if (s == sb[c]) {   // warp-uniform: flush segment ending at s-1
                atomicAdd(g_Acc + (size_t)(b * 144 + hc[c] * 12 + c) * EMB + j, acc[c]);
                acc[c] = 0.0f;
                hc[c]++;
            }
            acc[c] += v;
        }
    }
    #pragma unroll
    for (int c = 0; c < 12; c++)
        atomicAdd(g_Acc + (size_t)(b * 144 + hc[c] * 12 + c) * EMB + j, acc[c]);
}

// ---------------------------------------------------------------------------
// K2: K-split GEMM.  grid = 144 blocks (c = blk/12, jt = blk%12), 256 threads.
// Ws = Wv[64c..64c+63][jt*64..+63], As = RS[0..47][c][jt*64..+63]
// partial[bh][d] = sum_k As[bh][k]*Ws[d][k]  -> atomicAdd into G.
// ---------------------------------------------------------------------------
__global__ void __launch_bounds__(256) kgemm_kernel(const float* __restrict__ Wv)
{
    const int c  = blockIdx.x / 12;
    const int jt = blockIdx.x % 12;
    const int t = threadIdx.x;

    __shared__ float Ws[64][65];
    __shared__ float As[48][65];

    #pragma unroll
    for (int i = 0; i < 4; i++) {
        int f = t + 256 * i;
        int r = f >> 4, c4 = f & 15;
        float4 v = *(const float4*)(Wv + (size_t)(64 * c + r) * EMB + jt * 64 + c4 * 4);
        Ws[r][c4 * 4 + 0] = v.x; Ws[r][c4 * 4 + 1] = v.y;
        Ws[r][c4 * 4 + 2] = v.z; Ws[r][c4 * 4 + 3] = v.w;
    }
    #pragma unroll
    for (int i = 0; i < 3; i++) {
        int f = t + 256 * i;
        int r = f >> 4, c4 = f & 15;     // r = bh 0..47
        float4 v = *(const float4*)(g_Acc + ((size_t)r * HEADS + c) * EMB + jt * 64 + c4 * 4);
        As[r][c4 * 4 + 0] = v.x; As[r][c4 * 4 + 1] = v.y;
        As[r][c4 * 4 + 2] = v.z; As[r][c4 * 4 + 3] = v.w;
    }
    __syncthreads();

    const int tx = t & 15;     // 4 d's
    const int ty = t >> 4;     // 3 bh's

    float acc[3][4] = {};
    #pragma unroll 8
    for (int k = 0; k < 64; k++) {
        float a[3], bb[4];
        #pragma unroll
        for (int u = 0; u < 3; u++) a[u] = As[ty * 3 + u][k];
        #pragma unroll
        for (int v = 0; v < 4; v++) bb[v] = Ws[tx * 4 + v][k];
        #pragma unroll
        for (int u = 0; u < 3; u++)
            #pragma unroll
            for (int v = 0; v < 4; v++)
                acc[u][v] = fmaf(a[u], bb[v], acc[u][v]);
    }

    #pragma unroll
    for (int u = 0; u < 3; u++) {
        int bh = ty * 3 + u;
        int b = bh / HEADS, h = bh % HEADS;
        float* gp = g_Acc + RS_ELEMS + b * EMB + h * HDIM + tx * 4;
        #pragma unroll
        for (int v = 0; v < 4; v++)
            atomicAdd(gp + v, acc[u][v]);
    }
}

// ---------------------------------------------------------------------------
// K3: out[b, q, :] = G[b, :].  256 blocks x 192 threads; each thread loads its
// G float4 once and issues 16 independent row stores.
// ---------------------------------------------------------------------------
__global__ void __launch_bounds__(192) broadcast_kernel(float* __restrict__ out)
{
    const int row0 = blockIdx.x * 16;          // 16 | 1024 -> single b per block
    const int b = row0 >> 10;
    const int c4 = threadIdx.x;

    const float4 v = ((const float4*)(g_Acc + RS_ELEMS + b * EMB))[c4];
    float4* o = (float4*)(out + (size_t)row0 * EMB) + c4;
    #pragma unroll
    for (int i = 0; i < 16; i++)
        o[(size_t)i * 192] = v;
}

// ---------------------------------------------------------------------------
extern "C" void kernel_launch(void* const* d_in, const int* in_sizes, int n_in,
                              void* d_out, int out_size)
{
    // metadata order: key, query, value, Wk, Wq, Wv
    const float* value = (const float*)d_in[2];
    const float* Wv    = (const float*)d_in[5];
    float* out = (float*)d_out;

    float* acc;
    cudaGetSymbolAddress((void**)&acc, g_Acc);

    cudaMemsetAsync(acc, 0, (RS_ELEMS + G_ELEMS) * sizeof(float));
    scan_kernel<<<256, 384>>>(value);
    kgemm_kernel<<<144, 256>>>(Wv);
    broadcast_kernel<<<256, 192>>>(out);
}

// round 7
// speedup vs baseline: 1.4195x; 1.1550x over previous
#include <cuda_runtime.h>
#include <cstdint>

#define BATCH 4
#define SEQ   1024
#define EMB   768
#define HEADS 12
#define HDIM  64
#define BH    (BATCH*HEADS)    // 48
#define TROWS 16               // scan tile rows

#define RS_ELEMS (BH * HEADS * EMB)      // RS[(b*12+h)*12+c][j]
#define G_ELEMS  (BATCH * EMB)

// Zero-restoring invariant (no memset launch needed):
//  - module load zero-inits g_Acc
//  - scan zeroes G (block 0), atomically accumulates RS
//  - kgemm reads RS then zeroes its disjoint slice; atomically accumulates G
//  - broadcast reads G; next call's scan re-zeroes G
__device__ float g_Acc[RS_ELEMS + G_ELEMS];

// ---------------------------------------------------------------------------
// K1: prefix-snapshot segmented scan.
// grid = 512: x = ((b*64 + tile) << 1) | jhalf ; block = 384 threads (j).
// One running prefix per thread; <=2 uniform cut rows per tile; all 12 per-c
// range contributions reconstructed from {snapA, snapB, total}.
// ---------------------------------------------------------------------------
__global__ void __launch_bounds__(384) scan_kernel(const float* __restrict__ value)
{
    const int x  = blockIdx.x;
    const int jh = x & 1;
    const int bt = x >> 1;
    const int b  = bt >> 6;          // 0..3
    const int t  = bt & 63;          // 64 tiles of 16 rows
    const int j  = jh * 384 + threadIdx.x;

    // block (b=0,t=0,jh both) zero G: 768 float4 total, jh picks half
    if (bt == 0) {
        float4* Gz = (float4*)(g_Acc + RS_ELEMS) + jh * 384 + threadIdx.x;
        *Gz = make_float4(0.f, 0.f, 0.f, 0.f);
    }

    const int s0 = t * TROWS;
    const float* vp = value + ((size_t)b * SEQ + s0) * EMB + j;

    // per-c geometry (uniform across threads)
    int h0[12], sb[12];
    int m1 = 1 << 30, m2 = -1;
    #pragma unroll
    for (int c = 0; c < 12; c++) {
        h0[c] = (768 * s0 + 64 * c) >> 16;
        sb[c] = (65536 * (h0[c] + 1) - 64 * c + 767) / 768;
        if (sb[c] < s0 + TROWS) {      // boundary inside tile (sb > s0 always)
            m1 = min(m1, sb[c]);
            m2 = max(m2, sb[c]);
        }
    }

    float acc = 0.0f, snapA = 0.0f, snapB = 0.0f;
    #pragma unroll
    for (int i = 0; i < TROWS; i++) {
        const int s = s0 + i;
        if (s == m1) snapA = acc;
        if (s == m2) snapB = acc;
        acc += vp[(size_t)i * EMB];
    }

    float* RS = g_Acc;
    #pragma unroll
    for (int c = 0; c < 12; c++) {
        const size_t base = ((size_t)(b * 144 + h0[c] * 12 + c)) * EMB + j;
        if (sb[c] < s0 + TROWS) {
            const float lo = (sb[c] == m1) ? snapA : snapB;
            atomicAdd(RS + base, lo);
            atomicAdd(RS + base + 12 * EMB, acc - lo);   // h0+1 bin
        } else {
            atomicAdd(RS + base, acc);
        }
    }
}

// ---------------------------------------------------------------------------
// K2: K-split GEMM.  grid = 144 (c = blk/12, jt = blk%12), 256 threads.
// Stages RS slice to smem, zeroes it in gmem (restores invariant), MMA with
// Wv slice, atomicAdd partials into G.
// ---------------------------------------------------------------------------
__global__ void __launch_bounds__(256) kgemm_kernel(const float* __restrict__ Wv)
{
    const int c  = blockIdx.x / 12;
    const int jt = blockIdx.x % 12;
    const int t = threadIdx.x;

    __shared__ float Ws[64][65];
    __shared__ float As[48][65];

    #pragma unroll
    for (int i = 0; i < 4; i++) {
        int f = t + 256 * i;
        int r = f >> 4, c4 = f & 15;
        float4 v = *(const float4*)(Wv + (size_t)(64 * c + r) * EMB + jt * 64 + c4 * 4);
        Ws[r][c4 * 4 + 0] = v.x; Ws[r][c4 * 4 + 1] = v.y;
        Ws[r][c4 * 4 + 2] = v.z; Ws[r][c4 * 4 + 3] = v.w;
    }
    #pragma unroll
    for (int i = 0; i < 3; i++) {
        int f = t + 256 * i;
        int r = f >> 4, c4 = f & 15;     // r = bh 0..47
        float* src = g_Acc + ((size_t)r * HEADS + c) * EMB + jt * 64 + c4 * 4;
        float4 v = *(const float4*)src;
        *(float4*)src = make_float4(0.f, 0.f, 0.f, 0.f);   // restore zero invariant
        As[r][c4 * 4 + 0] = v.x; As[r][c4 * 4 + 1] = v.y;
        As[r][c4 * 4 + 2] = v.z; As[r][c4 * 4 + 3] = v.w;
    }
    __syncthreads();

    const int tx = t & 15;     // 4 d's
    const int ty = t >> 4;     // 3 bh's

    float acc[3][4] = {};
    #pragma unroll 8
    for (int k = 0; k < 64; k++) {
        float a[3], bb[4];
        #pragma unroll
        for (int u = 0; u < 3; u++) a[u] = As[ty * 3 + u][k];
        #pragma unroll
        for (int v = 0; v < 4; v++) bb[v] = Ws[tx * 4 + v][k];
        #pragma unroll
        for (int u = 0; u < 3; u++)
            #pragma unroll
            for (int v = 0; v < 4; v++)
                acc[u][v] = fmaf(a[u], bb[v], acc[u][v]);
    }

    #pragma unroll
    for (int u = 0; u < 3; u++) {
        int bh = ty * 3 + u;
        int b = bh / HEADS, h = bh % HEADS;
        float* gp = g_Acc + RS_ELEMS + b * EMB + h * HDIM + tx * 4;
        #pragma unroll
        for (int v = 0; v < 4; v++)
            atomicAdd(gp + v, acc[u][v]);
    }
}

// ---------------------------------------------------------------------------
// K3: out[b, q, :] = G[b, :].  512 blocks x 192 threads, 8 rows per block.
// ---------------------------------------------------------------------------
__global__ void __launch_bounds__(192) broadcast_kernel(float* __restrict__ out)
{
    const int row0 = blockIdx.x * 8;           // 8 | 1024 -> single b per block
    const int b = row0 >> 10;
    const int c4 = threadIdx.x;

    const float4 v = ((const float4*)(g_Acc + RS_ELEMS + b * EMB))[c4];
    float4* o = (float4*)(out + (size_t)row0 * EMB) + c4;
    #pragma unroll
    for (int i = 0; i < 8; i++)
        o[(size_t)i * 192] = v;
}

// ---------------------------------------------------------------------------
extern "C" void kernel_launch(void* const* d_in, const int* in_sizes, int n_in,
                              void* d_out, int out_size)
{
    // metadata order: key, query, value, Wk, Wq, Wv
    const float* value = (const float*)d_in[2];
    const float* Wv    = (const float*)d_in[5];
    float* out = (float*)d_out;

    scan_kernel<<<512, 384>>>(value);
    kgemm_kernel<<<144, 256>>>(Wv);
    broadcast_kernel<<<512, 192>>>(out);
}

// round 8
// speedup vs baseline: 1.6335x; 1.1508x over previous
#include <cuda_runtime.h>
#include <cstdint>

#define BATCH 4
#define SEQ   1024
#define EMB   768
#define HEADS 12
#define HDIM  64
#define BH    (BATCH*HEADS)    // 48

#define RS_ELEMS (BH * HEADS * EMB)      // RS[(b*12+h)*12+c][j]
#define G_ELEMS  (BATCH * EMB)

// [0, RS_ELEMS) = RS (fully overwritten by scan each call)
// [RS_ELEMS, +G_ELEMS) = G (zeroed by scan block 0, atomically reduced by kgemm)
__device__ float g_Acc[RS_ELEMS + G_ELEMS];

// ---------------------------------------------------------------------------
// K1: per-segment scan, NO atomics.
// grid = 192: x = (b*12+h)*4 + q (j-quarter).  block = 192 thr = 4 rowlanes x
// 48 float4-cols.  Three monotone sub-loops accumulate S0/S1/S2 around the
// <=2 uniform cut rows; smem-reduce over rowlanes; 12 per-c sums recombined
// and stored with plain STG.128 (single writer per RS bin).
// ---------------------------------------------------------------------------
__global__ void __launch_bounds__(192) scan_kernel(const float* __restrict__ value)
{
    const int x  = blockIdx.x;
    const int q  = x & 3;
    const int bh = x >> 2;
    const int b = bh / HEADS, h = bh % HEADS;
    const int tid = threadIdx.x;
    const int col = tid % 48;
    const int rl  = tid / 48;

    // block 0 zeroes G (768 float4)
    if (x == 0) {
        float4* Gz = (float4*)(g_Acc + RS_ELEMS);
        #pragma unroll
        for (int i = 0; i < 4; i++)
            Gz[tid + 192 * i] = make_float4(0.f, 0.f, 0.f, 0.f);
    }

    // geometry (uniform): per-c row range [a(c), bend(c))
    const int f0 = h << 16;
    const int f1 = f0 + 65536;
    int aMin = 1 << 30, cut1 = 0, cut2 = 1 << 30, bMax = 0;
    #pragma unroll
    for (int c = 0; c < 12; c++) {
        int na = f0 - 64 * c;
        int a  = (na <= 0) ? 0 : (na + 767) / 768;
        int bd = (f1 - 64 * c - 64) / 768 + 1;
        if (bd > SEQ) bd = SEQ;
        aMin = min(aMin, a); cut1 = max(cut1, a);
        cut2 = min(cut2, bd); bMax = max(bMax, bd);
    }

    const float4* vp = (const float4*)(value + (size_t)b * SEQ * EMB) + q * 48 + col;

    float4 S0 = make_float4(0.f,0.f,0.f,0.f);
    float4 S1 = S0, S2 = S0;
    int s = aMin + rl;
    for (; s < cut1; s += 4) {
        float4 v = vp[(size_t)s * 192];
        S0.x += v.x; S0.y += v.y; S0.z += v.z; S0.w += v.w;
    }
    #pragma unroll 4
    for (; s < cut2; s += 4) {
        float4 v = vp[(size_t)s * 192];
        S1.x += v.x; S1.y += v.y; S1.z += v.z; S1.w += v.w;
    }
    for (; s < bMax; s += 4) {
        float4 v = vp[(size_t)s * 192];
        S2.x += v.x; S2.y += v.y; S2.z += v.z; S2.w += v.w;
    }

    __shared__ float4 red[4][3][48];
    red[rl][0][col] = S0;
    red[rl][1][col] = S1;
    red[rl][2][col] = S2;
    __syncthreads();

    // store phase: thread t -> col = t%48, g = t/48 handles c in {g, g+4, g+8}
    const int g = rl;    // reuse 0..3
    float4 T0 = red[0][0][col], T1 = red[0][1][col], T2 = red[0][2][col];
    #pragma unroll
    for (int r = 1; r < 4; r++) {
        float4 u;
        u = red[r][0][col]; T0.x+=u.x; T0.y+=u.y; T0.z+=u.z; T0.w+=u.w;
        u = red[r][1][col]; T1.x+=u.x; T1.y+=u.y; T1.z+=u.z; T1.w+=u.w;
        u = red[r][2][col]; T2.x+=u.x; T2.y+=u.y; T2.z+=u.z; T2.w+=u.w;
    }

    float4* RS4 = (float4*)g_Acc;
    #pragma unroll
    for (int k = 0; k < 3; k++) {
        const int c = g + 4 * k;
        int na = f0 - 64 * c;
        int a  = (na <= 0) ? 0 : (na + 767) / 768;
        int bd = (f1 - 64 * c - 64) / 768 + 1;
        if (bd > SEQ) bd = SEQ;

        float4 r = T1;
        if (a == aMin)  { r.x+=T0.x; r.y+=T0.y; r.z+=T0.z; r.w+=T0.w; }
        if (bd == bMax) { r.x+=T2.x; r.y+=T2.y; r.z+=T2.z; r.w+=T2.w; }

        RS4[(size_t)(bh * HEADS + c) * 192 + q * 48 + col] = r;
    }
}

// ---------------------------------------------------------------------------
// K2: K-split GEMM.  grid = 144 (c = blk/12, jt = blk%12), 256 threads.
// Ws = Wv[64c..+63][jt*64..+63], As = RS[0..47][c][jt*64..+63];
// partial[bh][d] -> atomicAdd into G.
// ---------------------------------------------------------------------------
__global__ void __launch_bounds__(256) kgemm_kernel(const float* __restrict__ Wv)
{
    const int c  = blockIdx.x / 12;
    const int jt = blockIdx.x % 12;
    const int t = threadIdx.x;

    __shared__ float Ws[64][65];
    __shared__ float As[48][65];

    #pragma unroll
    for (int i = 0; i < 4; i++) {
        int f = t + 256 * i;
        int r = f >> 4, c4 = f & 15;
        float4 v = *(const float4*)(Wv + (size_t)(64 * c + r) * EMB + jt * 64 + c4 * 4);
        Ws[r][c4 * 4 + 0] = v.x; Ws[r][c4 * 4 + 1] = v.y;
        Ws[r][c4 * 4 + 2] = v.z; Ws[r][c4 * 4 + 3] = v.w;
    }
    #pragma unroll
    for (int i = 0; i < 3; i++) {
        int f = t + 256 * i;
        int r = f >> 4, c4 = f & 15;     // r = bh 0..47
        float4 v = *(const float4*)(g_Acc + ((size_t)r * HEADS + c) * EMB + jt * 64 + c4 * 4);
        As[r][c4 * 4 + 0] = v.x; As[r][c4 * 4 + 1] = v.y;
        As[r][c4 * 4 + 2] = v.z; As[r][c4 * 4 + 3] = v.w;
    }
    __syncthreads();

    const int tx = t & 15;     // 4 d's
    const int ty = t >> 4;     // 3 bh's

    float acc[3][4] = {};
    #pragma unroll 8
    for (int k = 0; k < 64; k++) {
        float a[3], bb[4];
        #pragma unroll
        for (int u = 0; u < 3; u++) a[u] = As[ty * 3 + u][k];
        #pragma unroll
        for (int v = 0; v < 4; v++) bb[v] = Ws[tx * 4 + v][k];
        #pragma unroll
        for (int u = 0; u < 3; u++)
            #pragma unroll
            for (int v = 0; v < 4; v++)
                acc[u][v] = fmaf(a[u], bb[v], acc[u][v]);
    }

    #pragma unroll
    for (int u = 0; u < 3; u++) {
        int bh = ty * 3 + u;
        int b = bh / HEADS, hh = bh % HEADS;
        float* gp = g_Acc + RS_ELEMS + b * EMB + hh * HDIM + tx * 4;
        #pragma unroll
        for (int v = 0; v < 4; v++)
            atomicAdd(gp + v, acc[u][v]);
    }
}

// ---------------------------------------------------------------------------
// K3: out[b, q, :] = G[b, :].  512 blocks x 192 threads, 8 rows per block.
// ---------------------------------------------------------------------------
__global__ void __launch_bounds__(192) broadcast_kernel(float* __restrict__ out)
{
    const int row0 = blockIdx.x * 8;           // 8 | 1024 -> single b per block
    const int b = row0 >> 10;
    const int c4 = threadIdx.x;

    const float4 v = ((const float4*)(g_Acc + RS_ELEMS + b * EMB))[c4];
    float4* o = (float4*)(out + (size_t)row0 * EMB) + c4;
    #pragma unroll
    for (int i = 0; i < 8; i++)
        o[(size_t)i * 192] = v;
}

// ---------------------------------------------------------------------------
extern "C" void kernel_launch(void* const* d_in, const int* in_sizes, int n_in,
                              void* d_out, int out_size)
{
    // metadata order: key, query, value, Wk, Wq, Wv
    const float* value = (const float*)d_in[2];
    const float* Wv    = (const float*)d_in[5];
    float* out = (float*)d_out;

    scan_kernel<<<192, 192>>>(value);
    kgemm_kernel<<<144, 256>>>(Wv);
    broadcast_kernel<<<512, 192>>>(out);
}

// round 9
// speedup vs baseline: 1.6587x; 1.0154x over previous
#include <cuda_runtime.h>
#include <cstdint>

#define BATCH 4
#define SEQ   1024
#define EMB   768
#define HEADS 12
#define HDIM  64
#define BH    (BATCH*HEADS)    // 48
#define NSPL  4                // row-chunk replicas

#define RS_ONE   (BH * HEADS * EMB)          // one RS replica (442368 floats)
#define G_ELEMS  (BATCH * EMB)

// [0, 4*RS_ONE) = 4 RS replicas (each fully overwritten by scan every call)
// [4*RS_ONE, +G_ELEMS) = G (zeroed by scan block 0, atomic-reduced by kgemm)
__device__ float g_Acc[NSPL * RS_ONE + G_ELEMS];

// ---------------------------------------------------------------------------
// K1: per-(segment, j-quarter, row-chunk) scan, NO atomics.
// grid = 768: x = bh*16 + q*4 + rc.  block = 192 thr = 4 rowlanes x 48 cols.
// Three clamped monotone sub-loops (S0/S1/S2 around the <=2 uniform cuts);
// smem reduce over rowlanes; per-c recombination; STG.128 into replica rc.
// ---------------------------------------------------------------------------
__global__ void __launch_bounds__(192) scan_kernel(const float* __restrict__ value)
{
    const int x  = blockIdx.x;
    const int rc = x & 3;
    const int q  = (x >> 2) & 3;
    const int bh = x >> 4;
    const int b = bh / HEADS, h = bh % HEADS;
    const int tid = threadIdx.x;
    const int col = tid % 48;
    const int rl  = tid / 48;

    if (x == 0) {   // zero G (768 float4)
        float4* Gz = (float4*)(g_Acc + NSPL * RS_ONE);
        #pragma unroll
        for (int i = 0; i < 4; i++)
            Gz[tid + 192 * i] = make_float4(0.f, 0.f, 0.f, 0.f);
    }

    // geometry (uniform): per-c row range [a(c), bend(c))
    const int f0 = h << 16;
    const int f1 = f0 + 65536;
    int aMin = 1 << 30, cut1 = 0, cut2 = 1 << 30, bMax = 0;
    #pragma unroll
    for (int c = 0; c < 12; c++) {
        int na = f0 - 64 * c;
        int a  = (na <= 0) ? 0 : (na + 767) / 768;
        int bd = (f1 - 64 * c - 64) / 768 + 1;
        if (bd > SEQ) bd = SEQ;
        aMin = min(aMin, a); cut1 = max(cut1, a);
        cut2 = min(cut2, bd); bMax = max(bMax, bd);
    }

    const int L  = bMax - aMin;
    const int lo = aMin + (L * rc)     / NSPL;
    const int hi = aMin + (L * (rc+1)) / NSPL;

    const float4* vp = (const float4*)(value + (size_t)b * SEQ * EMB) + q * 48 + col;

    float4 S0 = make_float4(0.f,0.f,0.f,0.f);
    float4 S1 = S0, S2 = S0;

    {   // S0: [lo, min(hi,cut1))
        const int e = min(hi, cut1);
        for (int s = lo + rl; s < e; s += 4) {
            float4 v = vp[(size_t)s * 192];
            S0.x += v.x; S0.y += v.y; S0.z += v.z; S0.w += v.w;
        }
    }
    {   // S1: [max(lo,cut1), min(hi,cut2))
        const int st = max(lo, cut1), e = min(hi, cut2);
        #pragma unroll 4
        for (int s = st + rl; s < e; s += 4) {
            float4 v = vp[(size_t)s * 192];
            S1.x += v.x; S1.y += v.y; S1.z += v.z; S1.w += v.w;
        }
    }
    {   // S2: [max(lo,cut2), hi)
        const int st = max(lo, cut2);
        for (int s = st + rl; s < hi; s += 4) {
            float4 v = vp[(size_t)s * 192];
            S2.x += v.x; S2.y += v.y; S2.z += v.z; S2.w += v.w;
        }
    }

    __shared__ float4 red[4][3][48];
    red[rl][0][col] = S0;
    red[rl][1][col] = S1;
    red[rl][2][col] = S2;
    __syncthreads();

    float4 T0 = red[0][0][col], T1 = red[0][1][col], T2 = red[0][2][col];
    #pragma unroll
    for (int r = 1; r < 4; r++) {
        float4 u;
        u = red[r][0][col]; T0.x+=u.x; T0.y+=u.y; T0.z+=u.z; T0.w+=u.w;
        u = red[r][1][col]; T1.x+=u.x; T1.y+=u.y; T1.z+=u.z; T1.w+=u.w;
        u = red[r][2][col]; T2.x+=u.x; T2.y+=u.y; T2.z+=u.z; T2.w+=u.w;
    }

    float4* RS4 = (float4*)(g_Acc + (size_t)rc * RS_ONE);
    #pragma unroll
    for (int k = 0; k < 3; k++) {
        const int c = rl + 4 * k;
        int na = f0 - 64 * c;
        int a  = (na <= 0) ? 0 : (na + 767) / 768;
        int bd = (f1 - 64 * c - 64) / 768 + 1;
        if (bd > SEQ) bd = SEQ;

        float4 r = T1;
        if (a == aMin)  { r.x+=T0.x; r.y+=T0.y; r.z+=T0.z; r.w+=T0.w; }
        if (bd == bMax) { r.x+=T2.x; r.y+=T2.y; r.z+=T2.z; r.w+=T2.w; }

        RS4[(size_t)(bh * HEADS + c) * 192 + q * 48 + col] = r;
    }
}

// ---------------------------------------------------------------------------
// K2: K-split GEMM.  grid = 144 (c = blk/12, jt = blk%12), 256 threads.
// As = sum of 4 RS replicas' slices; Ws = Wv slice; atomicAdd partials into G.
// ---------------------------------------------------------------------------
__global__ void __launch_bounds__(256) kgemm_kernel(const float* __restrict__ Wv)
{
    const int c  = blockIdx.x / 12;
    const int jt = blockIdx.x % 12;
    const int t = threadIdx.x;

    __shared__ float Ws[64][65];
    __shared__ float As[48][65];

    #pragma unroll
    for (int i = 0; i < 4; i++) {
        int f = t + 256 * i;
        int r = f >> 4, c4 = f & 15;
        float4 v = *(const float4*)(Wv + (size_t)(64 * c + r) * EMB + jt * 64 + c4 * 4);
        Ws[r][c4 * 4 + 0] = v.x; Ws[r][c4 * 4 + 1] = v.y;
        Ws[r][c4 * 4 + 2] = v.z; Ws[r][c4 * 4 + 3] = v.w;
    }
    #pragma unroll
    for (int i = 0; i < 3; i++) {
        int f = t + 256 * i;
        int r = f >> 4, c4 = f & 15;     // r = bh 0..47
        const size_t off = ((size_t)r * HEADS + c) * EMB + jt * 64 + c4 * 4;
        float4 v = *(const float4*)(g_Acc + off);
        #pragma unroll
        for (int rc = 1; rc < NSPL; rc++) {
            float4 u = *(const float4*)(g_Acc + (size_t)rc * RS_ONE + off);
            v.x += u.x; v.y += u.y; v.z += u.z; v.w += u.w;
        }
        As[r][c4 * 4 + 0] = v.x; As[r][c4 * 4 + 1] = v.y;
        As[r][c4 * 4 + 2] = v.z; As[r][c4 * 4 + 3] = v.w;
    }
    __syncthreads();

    const int tx = t & 15;     // 4 d's
    const int ty = t >> 4;     // 3 bh's

    float acc[3][4] = {};
    #pragma unroll 8
    for (int k = 0; k < 64; k++) {
        float a[3], bb[4];
        #pragma unroll
        for (int u = 0; u < 3; u++) a[u] = As[ty * 3 + u][k];
        #pragma unroll
        for (int v = 0; v < 4; v++) bb[v] = Ws[tx * 4 + v][k];
        #pragma unroll
        for (int u = 0; u < 3; u++)
            #pragma unroll
            for (int v = 0; v < 4; v++)
                acc[u][v] = fmaf(a[u], bb[v], acc[u][v]);
    }

    #pragma unroll
    for (int u = 0; u < 3; u++) {
        int bh = ty * 3 + u;
        int b = bh / HEADS, hh = bh % HEADS;
        float* gp = g_Acc + NSPL * RS_ONE + b * EMB + hh * HDIM + tx * 4;
        #pragma unroll
        for (int v = 0; v < 4; v++)
            atomicAdd(gp + v, acc[u][v]);
    }
}

// ---------------------------------------------------------------------------
// K3: out[b, q, :] = G[b, :].  1024 blocks x 192 threads, 4 rows per block.
// ---------------------------------------------------------------------------
__global__ void __launch_bounds__(192) broadcast_kernel(float* __restrict__ out)
{
    const int row0 = blockIdx.x * 4;           // 4 | 1024 -> single b per block
    const int b = row0 >> 10;
    const int c4 = threadIdx.x;

    const float4 v = ((const float4*)(g_Acc + NSPL * RS_ONE + b * EMB))[c4];
    float4* o = (float4*)(out + (size_t)row0 * EMB) + c4;
    #pragma unroll
    for (int i = 0; i < 4; i++)
        o[(size_t)i * 192] = v;
}

// ---------------------------------------------------------------------------
extern "C" void kernel_launch(void* const* d_in, const int* in_sizes, int n_in,
                              void* d_out, int out_size)
{
    // metadata order: key, query, value, Wk, Wq, Wv
    const float* value = (const float*)d_in[2];
    const float* Wv    = (const float*)d_in[5];
    float* out = (float*)d_out;

    scan_kernel<<<768, 192>>>(value);
    kgemm_kernel<<<144, 256>>>(Wv);
    broadcast_kernel<<<1024, 192>>>(out);
}